// round 1
// baseline (speedup 1.0000x reference)
#include <cuda_runtime.h>

#define B_ROWS 8192
#define DIM    128
#define BM     128
#define BN     128
#define NCHUNKS 16          // column chunks
#define NTILES_PER_BLK 4    // 64 column tiles / 16 chunks
#define NEG_INF_F (-1e30f)
#define POS_INF_F ( 1e30f)
#define MARGIN_F  0.2f

// Cross-block per-row reduction state (monotone-encoded floats for exact atomics)
__device__ unsigned g_max_enc[B_ROWS];
__device__ unsigned g_min_enc[B_ROWS];
__device__ int g_ids_is_64;   // 1 if ids serialized as int64, 0 if int32

__device__ __forceinline__ unsigned enc_f(float f) {
    unsigned u = __float_as_uint(f);
    return (u & 0x80000000u) ? ~u : (u | 0x80000000u);
}
__device__ __forceinline__ float dec_f(unsigned u) {
    return __uint_as_float((u & 0x80000000u) ? (u & 0x7FFFFFFFu) : ~u);
}

// ---------------------------------------------------------------------------
// Kernel 1: init global reduction arrays + detect ids dtype.
// int64 little-endian values 0..511 -> every odd 32-bit word is 0.
// int32 random ids 0..511 -> essentially impossible that all 4096 odd words are 0.
// ---------------------------------------------------------------------------
__global__ void init_kernel(const unsigned* __restrict__ ids_words) {
    __shared__ int s_odd_nonzero[256];
    int tid = blockIdx.x * blockDim.x + threadIdx.x;
    // init reduction arrays (grid covers 8192)
    if (tid < B_ROWS) {
        g_max_enc[tid] = enc_f(NEG_INF_F);
        g_min_enc[tid] = enc_f(POS_INF_F);
    }
    // block 0 additionally does the dtype detection
    if (blockIdx.x == 0) {
        int any = 0;
        for (int i = threadIdx.x; i < B_ROWS / 2; i += 256) {
            if (ids_words[2 * i + 1] != 0u) any = 1;
        }
        s_odd_nonzero[threadIdx.x] = any;
        __syncthreads();
        for (int o = 128; o; o >>= 1) {
            if (threadIdx.x < o) s_odd_nonzero[threadIdx.x] |= s_odd_nonzero[threadIdx.x + o];
            __syncthreads();
        }
        if (threadIdx.x == 0) g_ids_is_64 = s_odd_nonzero[0] ? 0 : 1;
    }
}

__device__ __forceinline__ int load_id(const void* ids, int i, int is64) {
    if (is64) return (int)((const long long*)ids)[i];
    return ((const int*)ids)[i];
}

// ---------------------------------------------------------------------------
// Kernel 2: fused GEMM tile + masked row max/min.
// Block: 256 threads (16x16), each owns an 8x8 micro-tile of a 128x128 score tile.
// Smem: As[k][i], Bs[k][j] (k-major, loaded transposed, conflict-free LDS.128).
// ---------------------------------------------------------------------------
__global__ void __launch_bounds__(256, 1)
tile_kernel(const float* __restrict__ im, const void* __restrict__ ids) {
    extern __shared__ float smem[];
    float* As = smem;                 // [DIM][BM]  As[k*BM + i]
    float* Bs = smem + DIM * BM;      // [DIM][BN]  Bs[k*BN + j]
    __shared__ float smax[BM], smin[BM];
    __shared__ int   idr[BM], idc[BN];

    const int tid = threadIdx.x;
    const int m0  = blockIdx.y * BM;
    const int is64 = g_ids_is_64;

    if (tid < BM) {
        smax[tid] = NEG_INF_F;
        smin[tid] = POS_INF_F;
        idr[tid]  = load_id(ids, m0 + tid, is64);
    }

    // Load A tile transposed: As[k][row] = im[m0+row][k]
    // warp-iteration q: k4 = q&31 (float4 group), rowgroup = q>>5; lane -> row.
    const int w = tid >> 5, l = tid & 31;
#pragma unroll
    for (int it = 0; it < 16; ++it) {
        int q = w * 16 + it;
        int k4 = q & 31, rg = q >> 5;
        int row = rg * 32 + l;
        float4 v = *(const float4*)(im + (size_t)(m0 + row) * DIM + k4 * 4);
        As[(k4 * 4 + 0) * BM + row] = v.x;
        As[(k4 * 4 + 1) * BM + row] = v.y;
        As[(k4 * 4 + 2) * BM + row] = v.z;
        As[(k4 * 4 + 3) * BM + row] = v.w;
    }

    const int ty = tid >> 4, tx = tid & 15;

    for (int t = 0; t < NTILES_PER_BLK; ++t) {
        const int n0 = (blockIdx.x * NTILES_PER_BLK + t) * BN;
        __syncthreads();   // Bs free to overwrite; also orders A/ids (first iter)

        if (tid < BN) idc[tid] = load_id(ids, n0 + tid, is64);
#pragma unroll
        for (int it = 0; it < 16; ++it) {
            int q = w * 16 + it;
            int k4 = q & 31, rg = q >> 5;
            int row = rg * 32 + l;
            float4 v = *(const float4*)(im + (size_t)(n0 + row) * DIM + k4 * 4);
            Bs[(k4 * 4 + 0) * BN + row] = v.x;
            Bs[(k4 * 4 + 1) * BN + row] = v.y;
            Bs[(k4 * 4 + 2) * BN + row] = v.z;
            Bs[(k4 * 4 + 3) * BN + row] = v.w;
        }
        __syncthreads();

        float acc[8][8];
#pragma unroll
        for (int u = 0; u < 8; ++u)
#pragma unroll
            for (int v = 0; v < 8; ++v) acc[u][v] = 0.0f;

#pragma unroll 4
        for (int k = 0; k < DIM; ++k) {
            float4 a0 = *(const float4*)&As[k * BM + ty * 8];
            float4 a1 = *(const float4*)&As[k * BM + ty * 8 + 4];
            float4 b0 = *(const float4*)&Bs[k * BN + tx * 8];
            float4 b1 = *(const float4*)&Bs[k * BN + tx * 8 + 4];
            float a[8] = {a0.x, a0.y, a0.z, a0.w, a1.x, a1.y, a1.z, a1.w};
            float b[8] = {b0.x, b0.y, b0.z, b0.w, b1.x, b1.y, b1.z, b1.w};
#pragma unroll
            for (int u = 0; u < 8; ++u)
#pragma unroll
                for (int v = 0; v < 8; ++v)
                    acc[u][v] = fmaf(a[u], b[v], acc[u][v]);
        }

        // Masked per-row reduction of the 8x8 micro-tile, then across the
        // 16 tx-lanes (half-warp: xor 1,2,4,8 stays inside the 16-lane group).
#pragma unroll
        for (int u = 0; u < 8; ++u) {
            const int grow = m0 + ty * 8 + u;
            const int ridu = idr[ty * 8 + u];
            float vmax = NEG_INF_F, vmin = POS_INF_F;
#pragma unroll
            for (int v = 0; v < 8; ++v) {
                const int gcol = n0 + tx * 8 + v;
                float s = (grow == gcol) ? 0.0f : acc[u][v];   // zeroed diagonal
                if (ridu == idc[tx * 8 + v]) vmin = fminf(vmin, s);   // positive (incl. self)
                else                         vmax = fmaxf(vmax, s);   // negative
            }
#pragma unroll
            for (int o = 8; o; o >>= 1) {
                vmax = fmaxf(vmax, __shfl_xor_sync(0xffffffffu, vmax, o));
                vmin = fminf(vmin, __shfl_xor_sync(0xffffffffu, vmin, o));
            }
            if (tx == 0) {  // one writer per row -> no race
                smax[ty * 8 + u] = fmaxf(smax[ty * 8 + u], vmax);
                smin[ty * 8 + u] = fminf(smin[ty * 8 + u], vmin);
            }
        }
    }
    __syncthreads();

    if (tid < BM) {
        atomicMax(&g_max_enc[m0 + tid], enc_f(smax[tid]));
        atomicMin(&g_min_enc[m0 + tid], enc_f(smin[tid]));
    }
}

// ---------------------------------------------------------------------------
// Kernel 3: deterministic scalar reduction of the hinge loss.
// ---------------------------------------------------------------------------
__global__ void finalize_kernel(float* __restrict__ out) {
    __shared__ float part[256];
    float s = 0.0f;
    for (int i = threadIdx.x; i < B_ROWS; i += 256) {
        float max_neg = dec_f(g_max_enc[i]);
        float min_pos = dec_f(g_min_enc[i]);
        s += fmaxf(MARGIN_F + max_neg - min_pos, 0.0f);
    }
    part[threadIdx.x] = s;
    __syncthreads();
    for (int o = 128; o; o >>= 1) {
        if (threadIdx.x < o) part[threadIdx.x] += part[threadIdx.x + o];
        __syncthreads();
    }
    if (threadIdx.x == 0) out[0] = part[0];
}

extern "C" void kernel_launch(void* const* d_in, const int* in_sizes, int n_in,
                              void* d_out, int out_size) {
    const float* im  = (const float*)d_in[0];
    const void*  ids = d_in[1];

    static const size_t SMEM_BYTES = (size_t)2 * DIM * BM * sizeof(float);  // 128 KB
    cudaFuncSetAttribute(tile_kernel, cudaFuncAttributeMaxDynamicSharedMemorySize,
                         (int)SMEM_BYTES);

    init_kernel<<<B_ROWS / 256, 256>>>((const unsigned*)ids);
    tile_kernel<<<dim3(NCHUNKS, B_ROWS / BM), 256, SMEM_BYTES>>>(im, ids);
    finalize_kernel<<<1, 256>>>((float*)d_out);
}

// round 2
// speedup vs baseline: 3.2510x; 3.2510x over previous
#include <cuda_runtime.h>

#define B_ROWS 8192
#define DIM    128
#define BM     128
#define BN     128
#define LDS_   132            // padded row stride (floats) -> conflict-free fragment loads
#define NCHUNKS 16            // column chunks
#define NTILES_PER_BLK 4      // 64 column tiles / 16 chunks
#define NEG_INF_F (-1e30f)
#define POS_INF_F ( 1e30f)
#define MARGIN_F  0.2f

// Cross-block per-row reduction state (monotone-encoded floats for exact atomics)
__device__ unsigned g_max_enc[B_ROWS];
__device__ unsigned g_min_enc[B_ROWS];
__device__ int g_ids_is_64;   // 1 if ids serialized as int64, 0 if int32

__device__ __forceinline__ unsigned enc_f(float f) {
    unsigned u = __float_as_uint(f);
    return (u & 0x80000000u) ? ~u : (u | 0x80000000u);
}
__device__ __forceinline__ float dec_f(unsigned u) {
    return __uint_as_float((u & 0x80000000u) ? (u & 0x7FFFFFFFu) : ~u);
}
__device__ __forceinline__ unsigned f2tf32(float f) {
    unsigned u;
    asm("cvt.rna.tf32.f32 %0, %1;" : "=r"(u) : "f"(f));
    return u;
}

// ---------------------------------------------------------------------------
// Kernel 1: init global reduction arrays + detect ids dtype.
// ---------------------------------------------------------------------------
__global__ void init_kernel(const unsigned* __restrict__ ids_words) {
    __shared__ int s_odd_nonzero[256];
    int tid = blockIdx.x * blockDim.x + threadIdx.x;
    if (tid < B_ROWS) {
        g_max_enc[tid] = enc_f(NEG_INF_F);
        g_min_enc[tid] = enc_f(POS_INF_F);
    }
    if (blockIdx.x == 0) {
        int any = 0;
        for (int i = threadIdx.x; i < B_ROWS / 2; i += 256)
            if (ids_words[2 * i + 1] != 0u) any = 1;
        s_odd_nonzero[threadIdx.x] = any;
        __syncthreads();
        for (int o = 128; o; o >>= 1) {
            if (threadIdx.x < o) s_odd_nonzero[threadIdx.x] |= s_odd_nonzero[threadIdx.x + o];
            __syncthreads();
        }
        if (threadIdx.x == 0) g_ids_is_64 = s_odd_nonzero[0] ? 0 : 1;
    }
}

__device__ __forceinline__ int load_id(const void* ids, int i, int is64) {
    if (is64) return (int)((const long long*)ids)[i];
    return ((const int*)ids)[i];
}

// ---------------------------------------------------------------------------
// Kernel 2: TF32 tensor-core GEMM tile + fused masked row max/min.
// Block: 256 threads = 8 warps (4m x 2n), warp tile 32x64, mma m16n8k8.
// Both operands are im rows (scores = im @ im^T): A row-major [m][k],
// B col-major k x n == im rows [n][k]. tf32-converted at staging.
// ---------------------------------------------------------------------------
__global__ void __launch_bounds__(256, 1)
tile_kernel(const float* __restrict__ im, const void* __restrict__ ids) {
    extern __shared__ unsigned smem[];
    unsigned* As = smem;                 // [BM][LDS_] tf32 bits
    unsigned* Bs = smem + BM * LDS_;     // [BN][LDS_] tf32 bits
    __shared__ unsigned smaxE[BM], sminE[BM];
    __shared__ int idr[BM], idc[BN];

    const int tid = threadIdx.x;
    const int m0  = blockIdx.y * BM;
    const int is64 = g_ids_is_64;

    if (tid < BM) {
        smaxE[tid] = enc_f(NEG_INF_F);
        sminE[tid] = enc_f(POS_INF_F);
        idr[tid]   = load_id(ids, m0 + tid, is64);
    }

    // Stage A tile: rows m0..m0+127, convert fp32 -> tf32 bits.
#pragma unroll
    for (int it = 0; it < 16; ++it) {
        int idx = it * 256 + tid;
        int row = idx >> 5, c4 = idx & 31;
        float4 v = *(const float4*)(im + (size_t)(m0 + row) * DIM + c4 * 4);
        unsigned* dst = As + row * LDS_ + c4 * 4;
        dst[0] = f2tf32(v.x); dst[1] = f2tf32(v.y);
        dst[2] = f2tf32(v.z); dst[3] = f2tf32(v.w);
    }

    const int warp = tid >> 5, lane = tid & 31;
    const int wm = warp >> 1, wn = warp & 1;      // warp tile origin (wm*32, wn*64)
    const int g  = lane >> 2, tig = lane & 3;

    for (int t = 0; t < NTILES_PER_BLK; ++t) {
        const int n0 = (blockIdx.x * NTILES_PER_BLK + t) * BN;
        __syncthreads();   // Bs/idc free to overwrite

        if (tid < BN) idc[tid] = load_id(ids, n0 + tid, is64);
#pragma unroll
        for (int it = 0; it < 16; ++it) {
            int idx = it * 256 + tid;
            int row = idx >> 5, c4 = idx & 31;
            float4 v = *(const float4*)(im + (size_t)(n0 + row) * DIM + c4 * 4);
            unsigned* dst = Bs + row * LDS_ + c4 * 4;
            dst[0] = f2tf32(v.x); dst[1] = f2tf32(v.y);
            dst[2] = f2tf32(v.z); dst[3] = f2tf32(v.w);
        }
        __syncthreads();

        float acc[2][8][4];
#pragma unroll
        for (int mt = 0; mt < 2; ++mt)
#pragma unroll
            for (int nt = 0; nt < 8; ++nt)
#pragma unroll
                for (int r = 0; r < 4; ++r) acc[mt][nt][r] = 0.0f;

#pragma unroll
        for (int ks = 0; ks < 16; ++ks) {
            const int k0 = ks * 8;
            unsigned a[2][4];
#pragma unroll
            for (int mt = 0; mt < 2; ++mt) {
                const unsigned* ap = As + (wm * 32 + mt * 16 + g) * LDS_ + k0 + tig;
                a[mt][0] = ap[0];
                a[mt][1] = ap[8 * LDS_];
                a[mt][2] = ap[4];
                a[mt][3] = ap[8 * LDS_ + 4];
            }
            unsigned b[8][2];
#pragma unroll
            for (int nt = 0; nt < 8; ++nt) {
                const unsigned* bp = Bs + (wn * 64 + nt * 8 + g) * LDS_ + k0 + tig;
                b[nt][0] = bp[0];
                b[nt][1] = bp[4];
            }
#pragma unroll
            for (int mt = 0; mt < 2; ++mt)
#pragma unroll
                for (int nt = 0; nt < 8; ++nt) {
                    asm volatile(
                        "mma.sync.aligned.m16n8k8.row.col.f32.tf32.tf32.f32 "
                        "{%0,%1,%2,%3}, {%4,%5,%6,%7}, {%8,%9}, {%0,%1,%2,%3};"
                        : "+f"(acc[mt][nt][0]), "+f"(acc[mt][nt][1]),
                          "+f"(acc[mt][nt][2]), "+f"(acc[mt][nt][3])
                        : "r"(a[mt][0]), "r"(a[mt][1]), "r"(a[mt][2]), "r"(a[mt][3]),
                          "r"(b[nt][0]), "r"(b[nt][1]));
                }
        }

        // Epilogue: masked per-row max(neg)/min(pos) over this warp's fragment.
        // c0,c1 -> row base+g ; c2,c3 -> row base+g+8 ; cols 2*tig, 2*tig+1.
#pragma unroll
        for (int mt = 0; mt < 2; ++mt) {
#pragma unroll
            for (int half = 0; half < 2; ++half) {
                const int lr   = wm * 32 + mt * 16 + g + half * 8;
                const int grow = m0 + lr;
                const int ridu = idr[lr];
                float vmax = NEG_INF_F, vmin = POS_INF_F;
#pragma unroll
                for (int nt = 0; nt < 8; ++nt) {
#pragma unroll
                    for (int e = 0; e < 2; ++e) {
                        const int lc = wn * 64 + nt * 8 + 2 * tig + e;
                        float s = (grow == n0 + lc) ? 0.0f : acc[mt][nt][half * 2 + e];
                        if (ridu == idc[lc]) vmin = fminf(vmin, s);
                        else                 vmax = fmaxf(vmax, s);
                    }
                }
                // combine across the 4 lanes of this group (tig = low 2 bits)
#pragma unroll
                for (int o = 1; o < 4; o <<= 1) {
                    vmax = fmaxf(vmax, __shfl_xor_sync(0xffffffffu, vmax, o));
                    vmin = fminf(vmin, __shfl_xor_sync(0xffffffffu, vmin, o));
                }
                if (tig == 0) {
                    atomicMax(&smaxE[lr], enc_f(vmax));
                    atomicMin(&sminE[lr], enc_f(vmin));
                }
            }
        }
    }
    __syncthreads();

    if (tid < BM) {
        atomicMax(&g_max_enc[m0 + tid], smaxE[tid]);
        atomicMin(&g_min_enc[m0 + tid], sminE[tid]);
    }
}

// ---------------------------------------------------------------------------
// Kernel 3: deterministic scalar reduction of the hinge loss.
// ---------------------------------------------------------------------------
__global__ void finalize_kernel(float* __restrict__ out) {
    __shared__ float part[256];
    float s = 0.0f;
    for (int i = threadIdx.x; i < B_ROWS; i += 256) {
        float max_neg = dec_f(g_max_enc[i]);
        float min_pos = dec_f(g_min_enc[i]);
        s += fmaxf(MARGIN_F + max_neg - min_pos, 0.0f);
    }
    part[threadIdx.x] = s;
    __syncthreads();
    for (int o = 128; o; o >>= 1) {
        if (threadIdx.x < o) part[threadIdx.x] += part[threadIdx.x + o];
        __syncthreads();
    }
    if (threadIdx.x == 0) out[0] = part[0];
}

extern "C" void kernel_launch(void* const* d_in, const int* in_sizes, int n_in,
                              void* d_out, int out_size) {
    const float* im  = (const float*)d_in[0];
    const void*  ids = d_in[1];

    static const size_t SMEM_BYTES = (size_t)2 * BM * LDS_ * sizeof(unsigned);  // 132 KB
    cudaFuncSetAttribute(tile_kernel, cudaFuncAttributeMaxDynamicSharedMemorySize,
                         (int)SMEM_BYTES);

    init_kernel<<<B_ROWS / 256, 256>>>((const unsigned*)ids);
    tile_kernel<<<dim3(NCHUNKS, B_ROWS / BM), 256, SMEM_BYTES>>>(im, ids);
    finalize_kernel<<<1, 256>>>((float*)d_out);
}

// round 3
// speedup vs baseline: 4.7006x; 1.4459x over previous
#include <cuda_runtime.h>
#include <cuda_bf16.h>

#define B_ROWS 8192
#define DIM    128
#define BM     128
#define BN     128
#define SH     136            // halves per smem row (272 B) -> conflict-free fragment LDS
#define NEG_INF_F (-1e30f)
#define POS_INF_F ( 1e30f)
#define MARGIN_F  0.2f

// Cross-block per-row reduction state (monotone-encoded floats for exact atomics)
__device__ unsigned g_max_enc[B_ROWS];
__device__ unsigned g_min_enc[B_ROWS];
__device__ int g_ids_is_64;   // 1 if ids serialized as int64, 0 if int32

__device__ __forceinline__ unsigned enc_f(float f) {
    unsigned u = __float_as_uint(f);
    return (u & 0x80000000u) ? ~u : (u | 0x80000000u);
}
__device__ __forceinline__ float dec_f(unsigned u) {
    return __uint_as_float((u & 0x80000000u) ? (u & 0x7FFFFFFFu) : ~u);
}
__device__ __forceinline__ unsigned pack_bf16(float lo, float hi) {
    __nv_bfloat162 p = __floats2bfloat162_rn(lo, hi);  // lo -> .x (low half)
    return *(unsigned*)&p;
}

// ---------------------------------------------------------------------------
// Kernel 1: init global reduction arrays + fast ids-dtype detection.
// int64 little-endian ids (0..511) -> odd 32-bit words are all zero.
// ---------------------------------------------------------------------------
__global__ void init_kernel(const unsigned* __restrict__ ids_words) {
    int tid = blockIdx.x * blockDim.x + threadIdx.x;
    if (tid < B_ROWS) {
        g_max_enc[tid] = enc_f(NEG_INF_F);
        g_min_enc[tid] = enc_f(POS_INF_F);
    }
    if (blockIdx.x == 0 && threadIdx.x < 32) {
        // check 64 odd words; P(all zero | int32 random ids) ~ (1/512)^64 ~ 0
        unsigned w = ids_words[2 * threadIdx.x + 1] | ids_words[2 * threadIdx.x + 65];
        unsigned any = __ballot_sync(0xffffffffu, w != 0u);
        if (threadIdx.x == 0) g_ids_is_64 = (any == 0u) ? 1 : 0;
    }
}

__device__ __forceinline__ int load_id(const void* ids, int i, int is64) {
    if (is64) return (int)((const long long*)ids)[i];
    return ((const int*)ids)[i];
}

// ---------------------------------------------------------------------------
// Kernel 2: symmetric bf16 tensor-core tile + fused masked row/col max-min.
// Grid 64x64, only bj>=bi blocks work (upper triangle). Off-diagonal tiles
// serve BOTH (bi,bj) row-anchors and (bj,bi) col-anchors via the transpose.
// Block: 256 thr = 8 warps (4m x 2n), warp tile 32x64, mma m16n8k16 bf16.
// ---------------------------------------------------------------------------
__global__ void __launch_bounds__(256, 1)
tile_kernel(const float* __restrict__ im, const void* __restrict__ ids) {
    const int bi = blockIdx.y, bj = blockIdx.x;
    if (bj < bi) return;                       // lower triangle: no work
    const bool diag = (bi == bj);

    extern __shared__ unsigned short smem_h[];
    unsigned short* As = smem_h;               // [BM][SH] bf16
    unsigned short* Bs = smem_h + BM * SH;     // [BN][SH] bf16
    __shared__ unsigned smaxE[BM], sminE[BM];  // row-anchor partials
    __shared__ unsigned cmaxE[BN], cminE[BN];  // col-anchor partials
    __shared__ int idr[BM], idc[BN];

    const int tid  = threadIdx.x;
    const int m0   = bi * BM;
    const int n0   = bj * BN;
    const int is64 = g_ids_is_64;

    if (tid < BM) {
        smaxE[tid] = enc_f(NEG_INF_F); sminE[tid] = enc_f(POS_INF_F);
        cmaxE[tid] = enc_f(NEG_INF_F); cminE[tid] = enc_f(POS_INF_F);
        idr[tid] = load_id(ids, m0 + tid, is64);
        idc[tid] = load_id(ids, n0 + tid, is64);
    }

    // Stage both tiles, fp32 -> bf16. idx -> row = idx>>5, c4 = idx&31 (float4).
#pragma unroll
    for (int it = 0; it < 16; ++it) {
        int idx = it * 256 + tid;
        int row = idx >> 5, c4 = idx & 31;
        float4 va = *(const float4*)(im + (size_t)(m0 + row) * DIM + c4 * 4);
        unsigned* da = (unsigned*)(As + row * SH) + c4 * 2;
        da[0] = pack_bf16(va.x, va.y); da[1] = pack_bf16(va.z, va.w);
        float4 vb = *(const float4*)(im + (size_t)(n0 + row) * DIM + c4 * 4);
        unsigned* db = (unsigned*)(Bs + row * SH) + c4 * 2;
        db[0] = pack_bf16(vb.x, vb.y); db[1] = pack_bf16(vb.z, vb.w);
    }
    __syncthreads();

    const int warp = tid >> 5, lane = tid & 31;
    const int wm = warp >> 1, wn = warp & 1;      // warp tile origin (wm*32, wn*64)
    const int g  = lane >> 2, tig = lane & 3;

    float acc[2][8][4];
#pragma unroll
    for (int mt = 0; mt < 2; ++mt)
#pragma unroll
        for (int nt = 0; nt < 8; ++nt)
#pragma unroll
            for (int r = 0; r < 4; ++r) acc[mt][nt][r] = 0.0f;

    const unsigned short* Abase = As + (wm * 32 + g) * SH + 2 * tig;
    const unsigned short* Bbase = Bs + (wn * 64 + g) * SH + 2 * tig;

#pragma unroll
    for (int ks = 0; ks < 8; ++ks) {
        const int k0 = ks * 16;
        unsigned a[2][4];
#pragma unroll
        for (int mt = 0; mt < 2; ++mt) {
            const unsigned short* ap = Abase + mt * 16 * SH + k0;
            a[mt][0] = *(const unsigned*)(ap);
            a[mt][1] = *(const unsigned*)(ap + 8 * SH);
            a[mt][2] = *(const unsigned*)(ap + 8);
            a[mt][3] = *(const unsigned*)(ap + 8 * SH + 8);
        }
        unsigned b[8][2];
#pragma unroll
        for (int nt = 0; nt < 8; ++nt) {
            const unsigned short* bp = Bbase + nt * 8 * SH + k0;
            b[nt][0] = *(const unsigned*)(bp);
            b[nt][1] = *(const unsigned*)(bp + 8);
        }
#pragma unroll
        for (int mt = 0; mt < 2; ++mt)
#pragma unroll
            for (int nt = 0; nt < 8; ++nt) {
                asm volatile(
                    "mma.sync.aligned.m16n8k16.row.col.f32.bf16.bf16.f32 "
                    "{%0,%1,%2,%3}, {%4,%5,%6,%7}, {%8,%9}, {%0,%1,%2,%3};"
                    : "+f"(acc[mt][nt][0]), "+f"(acc[mt][nt][1]),
                      "+f"(acc[mt][nt][2]), "+f"(acc[mt][nt][3])
                    : "r"(a[mt][0]), "r"(a[mt][1]), "r"(a[mt][2]), "r"(a[mt][3]),
                      "r"(b[nt][0]), "r"(b[nt][1]));
            }
    }

    // Fragment mapping: acc[mt][nt][h*2+e] -> row wm*32+mt*16+g+h*8, col wn*64+nt*8+2*tig+e.
    // --- Row-anchor epilogue (anchors m0+row, candidates n0+col) ---
#pragma unroll
    for (int mt = 0; mt < 2; ++mt) {
#pragma unroll
        for (int half = 0; half < 2; ++half) {
            const int lr   = wm * 32 + mt * 16 + g + half * 8;
            const int grow = m0 + lr;
            const int ridu = idr[lr];
            float vmax = NEG_INF_F, vmin = POS_INF_F;
#pragma unroll
            for (int nt = 0; nt < 8; ++nt) {
#pragma unroll
                for (int e = 0; e < 2; ++e) {
                    const int lc = wn * 64 + nt * 8 + 2 * tig + e;
                    float s = (grow == n0 + lc) ? 0.0f : acc[mt][nt][half * 2 + e];
                    if (ridu == idc[lc]) vmin = fminf(vmin, s);
                    else                 vmax = fmaxf(vmax, s);
                }
            }
#pragma unroll
            for (int o = 1; o < 4; o <<= 1) {   // reduce over tig (cols)
                vmax = fmaxf(vmax, __shfl_xor_sync(0xffffffffu, vmax, o));
                vmin = fminf(vmin, __shfl_xor_sync(0xffffffffu, vmin, o));
            }
            if (tig == 0) {
                atomicMax(&smaxE[lr], enc_f(vmax));
                atomicMin(&sminE[lr], enc_f(vmin));
            }
        }
    }

    // --- Col-anchor epilogue (transpose; off-diagonal tiles only) ---
    if (!diag) {
        int rid4[4];
#pragma unroll
        for (int q = 0; q < 4; ++q) rid4[q] = idr[wm * 32 + q * 8 + g];
#pragma unroll
        for (int nt = 0; nt < 8; ++nt) {
#pragma unroll
            for (int e = 0; e < 2; ++e) {
                const int lc  = wn * 64 + nt * 8 + 2 * tig + e;
                const int cid = idc[lc];
                float vmax = NEG_INF_F, vmin = POS_INF_F;
#pragma unroll
                for (int mt = 0; mt < 2; ++mt)
#pragma unroll
                    for (int half = 0; half < 2; ++half) {
                        float s = acc[mt][nt][half * 2 + e];
                        if (rid4[mt * 2 + half] == cid) vmin = fminf(vmin, s);
                        else                            vmax = fmaxf(vmax, s);
                    }
#pragma unroll
                for (int o = 4; o < 32; o <<= 1) {  // reduce over g (rows)
                    vmax = fmaxf(vmax, __shfl_xor_sync(0xffffffffu, vmax, o));
                    vmin = fminf(vmin, __shfl_xor_sync(0xffffffffu, vmin, o));
                }
                if (g == 0) {
                    atomicMax(&cmaxE[lc], enc_f(vmax));
                    atomicMin(&cminE[lc], enc_f(vmin));
                }
            }
        }
    }
    __syncthreads();

    if (tid < BM) {
        atomicMax(&g_max_enc[m0 + tid], smaxE[tid]);
        atomicMin(&g_min_enc[m0 + tid], sminE[tid]);
    }
    if (!diag && tid < BN) {
        atomicMax(&g_max_enc[n0 + tid], cmaxE[tid]);
        atomicMin(&g_min_enc[n0 + tid], cminE[tid]);
    }
}

// ---------------------------------------------------------------------------
// Kernel 3: deterministic scalar reduction of the hinge loss.
// ---------------------------------------------------------------------------
__global__ void finalize_kernel(float* __restrict__ out) {
    __shared__ float part[256];
    float s = 0.0f;
    for (int i = threadIdx.x; i < B_ROWS; i += 256) {
        float max_neg = dec_f(g_max_enc[i]);
        float min_pos = dec_f(g_min_enc[i]);
        s += fmaxf(MARGIN_F + max_neg - min_pos, 0.0f);
    }
    part[threadIdx.x] = s;
    __syncthreads();
    for (int o = 128; o; o >>= 1) {
        if (threadIdx.x < o) part[threadIdx.x] += part[threadIdx.x + o];
        __syncthreads();
    }
    if (threadIdx.x == 0) out[0] = part[0];
}

extern "C" void kernel_launch(void* const* d_in, const int* in_sizes, int n_in,
                              void* d_out, int out_size) {
    const float* im  = (const float*)d_in[0];
    const void*  ids = d_in[1];

    static const size_t SMEM_BYTES = (size_t)2 * BM * SH * sizeof(unsigned short); // ~68 KB
    cudaFuncSetAttribute(tile_kernel, cudaFuncAttributeMaxDynamicSharedMemorySize,
                         (int)SMEM_BYTES);

    init_kernel<<<B_ROWS / 256, 256>>>((const unsigned*)ids);
    tile_kernel<<<dim3(64, 64), 256, SMEM_BYTES>>>(im, ids);
    finalize_kernel<<<1, 256>>>((float*)d_out);
}

// round 5
// speedup vs baseline: 6.7769x; 1.4417x over previous
#include <cuda_runtime.h>
#include <cuda_bf16.h>
#include <cstdint>

#define B_ROWS 8192
#define DIM    128
#define BM     128
#define SH     136            // halves per smem bf16 row (272 B): LDSM conflict-free
#define CW     132            // floats per smem score row (16B-aligned rows)
#define NTILES 2080           // 64*65/2 upper-triangle tiles
#define NEG_INF_F (-1e30f)
#define POS_INF_F ( 1e30f)
#define MARGIN_F  0.2f

// ---------------- device-global state ----------------
__device__ unsigned       g_max_enc[B_ROWS];
__device__ unsigned       g_min_enc[B_ROWS];
__device__ __nv_bfloat16  g_im_bf16[B_ROWS * DIM];   // 2 MB, L2-resident
__device__ int            g_ids32[B_ROWS];

__device__ __forceinline__ unsigned enc_f(float f) {
    unsigned u = __float_as_uint(f);
    return (u & 0x80000000u) ? ~u : (u | 0x80000000u);
}
__device__ __forceinline__ float dec_f(unsigned u) {
    return __uint_as_float((u & 0x80000000u) ? (u & 0x7FFFFFFFu) : ~u);
}
__device__ __forceinline__ uint32_t smem_u32(const void* p) {
    uint32_t a;
    asm("{ .reg .u64 t; cvta.to.shared.u64 t, %1; cvt.u32.u64 %0, t; }" : "=r"(a) : "l"(p));
    return a;
}
#define LDSM_X4(r0, r1, r2, r3, addr) \
    asm volatile("ldmatrix.sync.aligned.m8n8.x4.shared.b16 {%0,%1,%2,%3}, [%4];" \
                 : "=r"(r0), "=r"(r1), "=r"(r2), "=r"(r3) : "r"(addr))

// ---------------------------------------------------------------------------
// Kernel 1: convert im -> bf16 (persistent), ids -> int32, clear reductions.
// ids dtype detected per block via ballot over 64 odd words (int64 LE ids in
// [0,512) -> odd words all zero; int32 random -> essentially never).
// ---------------------------------------------------------------------------
__global__ void convert_kernel(const float* __restrict__ im, const void* __restrict__ ids) {
    __shared__ int s_is64;
    const int tid = blockIdx.x * blockDim.x + threadIdx.x;   // 512*256 threads

    if (blockIdx.x < 32) {   // blocks that touch ids / reduction arrays
        if (threadIdx.x < 32) {
            const unsigned* w = (const unsigned*)ids;
            unsigned v = w[2 * threadIdx.x + 1] | w[2 * threadIdx.x + 65];
            unsigned any = __ballot_sync(0xffffffffu, v != 0u);
            if (threadIdx.x == 0) s_is64 = (any == 0u) ? 1 : 0;
        }
        __syncthreads();
        g_max_enc[tid] = enc_f(NEG_INF_F);
        g_min_enc[tid] = enc_f(POS_INF_F);
        g_ids32[tid] = s_is64 ? (int)((const long long*)ids)[tid]
                              : ((const int*)ids)[tid];
    }
    // 8 floats per thread -> bf16
    const float4* src = (const float4*)im + (size_t)tid * 2;
    float4 v0 = src[0], v1 = src[1];
    __nv_bfloat162* dst = (__nv_bfloat162*)g_im_bf16 + (size_t)tid * 4;
    dst[0] = __floats2bfloat162_rn(v0.x, v0.y);
    dst[1] = __floats2bfloat162_rn(v0.z, v0.w);
    dst[2] = __floats2bfloat162_rn(v1.x, v1.y);
    dst[3] = __floats2bfloat162_rn(v1.z, v1.w);
}

// ---------------------------------------------------------------------------
// Kernel 2: symmetric bf16 mma.sync tile + smem-transpose epilogue.
// Linear triangular grid (2080 blocks). Block = 256 thr = 8 warps (4m x 2n),
// warp tile 32x64, mma m16n8k16, fragments fed by ldmatrix.x4.
// Epilogue: acc -> smem fp32 [128][CW]; threads 0..127 reduce rows (anchors
// m0+r), threads 128..255 reduce cols (anchors n0+c, off-diag only).
// ---------------------------------------------------------------------------
__global__ void __launch_bounds__(256, 2)
tile_kernel(void) {
    // map linear block id -> (bi, bj), bj >= bi
    int t = blockIdx.x, bi = 0;
    while (t >= 64 - bi) { t -= 64 - bi; ++bi; }
    const int bj = bi + t;
    const bool diag = (bi == bj);
    const int m0 = bi * BM, n0 = bj * BM;

    extern __shared__ char smem[];
    unsigned short* As = (unsigned short*)smem;          // [BM][SH]
    unsigned short* Bs = As + BM * SH;                   // [BM][SH]
    float*          Cs = (float*)smem;                   // [BM][CW], aliases A/B
    __shared__ int s_idr[BM], s_idc[BM];

    const int tid = threadIdx.x;
    if (tid < BM) {
        s_idr[tid] = g_ids32[m0 + tid];
        s_idc[tid] = g_ids32[n0 + tid];
    }

    // Stage bf16 tiles: 2048 x 16B each, STS.128 conflict-free.
#pragma unroll
    for (int it = 0; it < 8; ++it) {
        int idx = it * 256 + tid;
        int row = idx >> 4, q = idx & 15;        // q: 16B chunk in 256B row
        *(uint4*)(As + row * SH + q * 8) =
            *(const uint4*)(g_im_bf16 + (size_t)(m0 + row) * DIM + q * 8);
        *(uint4*)(Bs + row * SH + q * 8) =
            *(const uint4*)(g_im_bf16 + (size_t)(n0 + row) * DIM + q * 8);
    }
    __syncthreads();

    const int warp = tid >> 5, lane = tid & 31;
    const int wm = warp >> 1, wn = warp & 1;     // warp tile origin (wm*32, wn*64)
    const int g = lane >> 2, tig = lane & 3;
    const int grp = lane >> 3, rin = lane & 7;

    // ldmatrix per-lane base addresses (bytes)
    const uint32_t As32 = smem_u32(As), Bs32 = smem_u32(Bs);
    uint32_t aaddr[2], baddr[4];
#pragma unroll
    for (int mt = 0; mt < 2; ++mt)
        aaddr[mt] = As32 + 2 * ((wm * 32 + mt * 16 + (grp & 1) * 8 + rin) * SH + (grp >> 1) * 8);
#pragma unroll
    for (int q = 0; q < 4; ++q)
        baddr[q] = Bs32 + 2 * ((wn * 64 + 16 * q + (grp >> 1) * 8 + rin) * SH + (grp & 1) * 8);

    float acc[2][8][4];
#pragma unroll
    for (int mt = 0; mt < 2; ++mt)
#pragma unroll
        for (int nt = 0; nt < 8; ++nt)
#pragma unroll
            for (int r = 0; r < 4; ++r) acc[mt][nt][r] = 0.0f;

#pragma unroll
    for (int ks = 0; ks < 8; ++ks) {
        const uint32_t koff = ks * 32;           // 16 halves = 32 bytes
        unsigned a[2][4], b[8][2];
#pragma unroll
        for (int mt = 0; mt < 2; ++mt)
            LDSM_X4(a[mt][0], a[mt][1], a[mt][2], a[mt][3], aaddr[mt] + koff);
#pragma unroll
        for (int q = 0; q < 4; ++q)
            LDSM_X4(b[2 * q][0], b[2 * q][1], b[2 * q + 1][0], b[2 * q + 1][1], baddr[q] + koff);
#pragma unroll
        for (int mt = 0; mt < 2; ++mt)
#pragma unroll
            for (int nt = 0; nt < 8; ++nt) {
                asm volatile(
                    "mma.sync.aligned.m16n8k16.row.col.f32.bf16.bf16.f32 "
                    "{%0,%1,%2,%3}, {%4,%5,%6,%7}, {%8,%9}, {%0,%1,%2,%3};"
                    : "+f"(acc[mt][nt][0]), "+f"(acc[mt][nt][1]),
                      "+f"(acc[mt][nt][2]), "+f"(acc[mt][nt][3])
                    : "r"(a[mt][0]), "r"(a[mt][1]), "r"(a[mt][2]), "r"(a[mt][3]),
                      "r"(b[nt][0]), "r"(b[nt][1]));
            }
    }
    __syncthreads();   // done reading As/Bs; Cs may overwrite

    // Scatter acc to Cs: row = wm*32+mt*16+g+half*8, cols wn*64+nt*8+2*tig+{0,1}
#pragma unroll
    for (int mt = 0; mt < 2; ++mt)
#pragma unroll
        for (int half = 0; half < 2; ++half) {
            const int lr = wm * 32 + mt * 16 + g + half * 8;
#pragma unroll
            for (int nt = 0; nt < 8; ++nt) {
                float2 v = make_float2(acc[mt][nt][half * 2], acc[mt][nt][half * 2 + 1]);
                *(float2*)(Cs + lr * CW + wn * 64 + nt * 8 + 2 * tig) = v;
            }
        }
    __syncthreads();

    if (tid < BM) {
        // Row-anchor: anchor m0+tid, candidates n0+c
        const int aid = s_idr[tid];
        float vmax = NEG_INF_F, vmin = POS_INF_F;
#pragma unroll 8
        for (int c4 = 0; c4 < 32; ++c4) {
            float4 v = *(const float4*)(Cs + tid * CW + c4 * 4);
            float sv[4] = {v.x, v.y, v.z, v.w};
#pragma unroll
            for (int j = 0; j < 4; ++j) {
                int c = c4 * 4 + j;
                float s = (diag && c == tid) ? 0.0f : sv[j];
                if (aid == s_idc[c]) vmin = fminf(vmin, s);
                else                 vmax = fmaxf(vmax, s);
            }
        }
        atomicMax(&g_max_enc[m0 + tid], enc_f(vmax));
        atomicMin(&g_min_enc[m0 + tid], enc_f(vmin));
    } else if (!diag) {
        // Col-anchor: anchor n0+c, candidates m0+r (transpose view)
        const int c = tid - BM;
        const int aid = s_idc[c];
        float vmax = NEG_INF_F, vmin = POS_INF_F;
#pragma unroll 8
        for (int r = 0; r < BM; ++r) {
            float s = Cs[r * CW + c];
            if (aid == s_idr[r]) vmin = fminf(vmin, s);
            else                 vmax = fmaxf(vmax, s);
        }
        atomicMax(&g_max_enc[n0 + c], enc_f(vmax));
        atomicMin(&g_min_enc[n0 + c], enc_f(vmin));
    }
}

// ---------------------------------------------------------------------------
// Kernel 3: deterministic scalar reduction of the hinge loss.
// ---------------------------------------------------------------------------
__global__ void finalize_kernel(float* __restrict__ out) {
    __shared__ float part[1024];
    float s = 0.0f;
    for (int i = threadIdx.x; i < B_ROWS; i += 1024) {
        s += fmaxf(MARGIN_F + dec_f(g_max_enc[i]) - dec_f(g_min_enc[i]), 0.0f);
    }
    part[threadIdx.x] = s;
    __syncthreads();
    for (int o = 512; o; o >>= 1) {
        if (threadIdx.x < o) part[threadIdx.x] += part[threadIdx.x + o];
        __syncthreads();
    }
    if (threadIdx.x == 0) out[0] = part[0];
}

extern "C" void kernel_launch(void* const* d_in, const int* in_sizes, int n_in,
                              void* d_out, int out_size) {
    const float* im  = (const float*)d_in[0];
    const void*  ids = d_in[1];

    static const int SMEM_BYTES = 2 * BM * SH * 2;   // 69632 B (Cs fits inside)
    cudaFuncSetAttribute(tile_kernel, cudaFuncAttributeMaxDynamicSharedMemorySize, SMEM_BYTES);

    convert_kernel<<<512, 256>>>(im, ids);
    tile_kernel<<<NTILES, 256, SMEM_BYTES>>>();
    finalize_kernel<<<1, 1024>>>((float*)d_out);
}